// round 17
// baseline (speedup 1.0000x reference)
#include <cuda_runtime.h>
#include <cuda_bf16.h>

// Problem shape (fixed by the reference)
#define BB 16
#define TT 4096
#define HH 512
#define SS 32            // T-chunks per batch (128 rows each)
#define TC (TT / SS)     // 128 rows per chunk
#define H4 (HH / 4)      // 128 float4 per row
#define NF4 (2 * HH / 4) // 256 float4 per chunk-partial
#define CP 8             // pass-2 chunk-splits  (SS/CP = 4 chunks per thread)
#define COLP 2           // pass-2 column-splits (each CTA: 128 float4-cols)

// Scratch: per (b, chunk): 512 global-sum + 512 local-sum floats (2 MiB)
__device__ float g_partial[BB * SS * 2 * HH];
__device__ int   g_counts[BB * SS];

// Pass 1: each CTA handles one contiguous (b, 128-row chunk); 128 threads x
// float4 cover H=512. Region A is 4-row-batched with branch-free fma accum
// (deep MLP); region B fetches only masked rows (warp-uniform skip).
// First 32 CTAs zero out[] for pass-2's atomics.
__global__ __launch_bounds__(128) void pass1_kernel(
    const float4* __restrict__ x,
    const int* __restrict__ lengths,
    const int* __restrict__ mask,        // jax bool materialized as int32
    float4* __restrict__ out4)           // [B*2H/4] — zeroed here
{
    const int blk = blockIdx.x;          // 0 .. B*SS-1
    const int b   = blk / SS;
    const int s   = blk % SS;
    const int tid = threadIdx.x;         // 0..127

    if (blk < 32) out4[blk * 128 + tid] = make_float4(0.f, 0.f, 0.f, 0.f);

    const int L  = lengths[b];
    const int t0 = s * TC;
    int Lc = L - t0;
    Lc = Lc < 0 ? 0 : (Lc > TC ? TC : Lc);

    const float4* __restrict__ xp = x + (size_t)b * TT * H4 + (size_t)t0 * H4 + tid;
    const int* __restrict__ mp = mask + (size_t)b * TT + t0;   // 512B-aligned

    float4 ag = make_float4(0.f, 0.f, 0.f, 0.f);
    float4 al = make_float4(0.f, 0.f, 0.f, 0.f);
    int cnt = 0;

    // ---- Region A: t < Lc. 4-row batches, branch-free accumulation. ----
    const int LcA = Lc & ~3;
    int t = 0;
    #pragma unroll 2
    for (; t < LcA; t += 4) {
        const float4 v0 = xp[(size_t)(t + 0) * H4];
        const float4 v1 = xp[(size_t)(t + 1) * H4];
        const float4 v2 = xp[(size_t)(t + 2) * H4];
        const float4 v3 = xp[(size_t)(t + 3) * H4];
        const int4 mm = *reinterpret_cast<const int4*>(mp + t);

        ag.x += (v0.x + v1.x) + (v2.x + v3.x);
        ag.y += (v0.y + v1.y) + (v2.y + v3.y);
        ag.z += (v0.z + v1.z) + (v2.z + v3.z);
        ag.w += (v0.w + v1.w) + (v2.w + v3.w);

        const float w0 = mm.x ? 1.f : 0.f;
        const float w1 = mm.y ? 1.f : 0.f;
        const float w2 = mm.z ? 1.f : 0.f;
        const float w3 = mm.w ? 1.f : 0.f;
        al.x = fmaf(w0, v0.x, fmaf(w1, v1.x, fmaf(w2, v2.x, fmaf(w3, v3.x, al.x))));
        al.y = fmaf(w0, v0.y, fmaf(w1, v1.y, fmaf(w2, v2.y, fmaf(w3, v3.y, al.y))));
        al.z = fmaf(w0, v0.z, fmaf(w1, v1.z, fmaf(w2, v2.z, fmaf(w3, v3.z, al.z))));
        al.w = fmaf(w0, v0.w, fmaf(w1, v1.w, fmaf(w2, v2.w, fmaf(w3, v3.w, al.w))));
        cnt += (mm.x ? 1 : 0) + (mm.y ? 1 : 0) + (mm.z ? 1 : 0) + (mm.w ? 1 : 0);
    }
    for (; t < Lc; ++t) {                // remainder (0-3 rows)
        float4 v = xp[(size_t)t * H4];
        ag.x += v.x; ag.y += v.y; ag.z += v.z; ag.w += v.w;
        if (mp[t] != 0) { al.x += v.x; al.y += v.y; al.z += v.z; al.w += v.w; cnt++; }
    }
    // ---- Region B: t >= Lc — fetch only masked rows (uniform skip). ----
    #pragma unroll 4
    for (; t < TC; ++t) {
        if (mp[t] != 0) {
            float4 v = xp[(size_t)t * H4];
            al.x += v.x; al.y += v.y; al.z += v.z; al.w += v.w; cnt++;
        }
    }

    float4* outp = reinterpret_cast<float4*>(g_partial) + (size_t)blk * NF4;
    outp[tid]      = ag;
    outp[H4 + tid] = al;
    if (tid == 0) g_counts[blk] = cnt;
}

// Pass 2: 256 CTAs = (b, colpart, chunkpart); 128 threads. 4 float4 partial
// loads per thread; counts via one warp-shuffle reduce; pre-divide; 4 scalar
// atomicAdds into out (8 colliders per address).
__global__ __launch_bounds__(128) void pass2_kernel(
    const int* __restrict__ lengths,
    float* __restrict__ out)
{
    const int blk       = blockIdx.x;
    const int b         = blk / (COLP * CP);
    const int colpart   = (blk / CP) % COLP;   // 0: global half, 1: local half
    const int chunkpart = blk % CP;
    const int tid       = threadIdx.x;
    const int fc        = colpart * 128 + tid; // float4-column in [0, 256)

    __shared__ float s_inv;

    if (colpart == 1) {
        if (tid < 32) {
            int c = g_counts[b * SS + tid];
            #pragma unroll
            for (int d = 16; d >= 1; d >>= 1)
                c += __shfl_xor_sync(0xffffffffu, c, d);
            if (tid == 0) s_inv = 1.0f / (float)(c > 1 ? c : 1);
        }
    } else {
        if (tid == 0) {
            const int L = lengths[b];
            s_inv = 1.0f / (float)(L > 1 ? L : 1);
        }
    }

    const int c0 = chunkpart * (SS / CP);
    const float4* p = reinterpret_cast<const float4*>(g_partial)
                    + ((size_t)b * SS + c0) * NF4 + fc;

    float4 acc = make_float4(0.f, 0.f, 0.f, 0.f);
    #pragma unroll
    for (int c = 0; c < SS / CP; ++c) {
        float4 v = p[(size_t)c * NF4];
        acc.x += v.x; acc.y += v.y; acc.z += v.z; acc.w += v.w;
    }

    __syncthreads();
    const float inv = s_inv;

    float* o = out + (size_t)b * 2 * HH + 4 * fc;
    atomicAdd(&o[0], acc.x * inv);
    atomicAdd(&o[1], acc.y * inv);
    atomicAdd(&o[2], acc.z * inv);
    atomicAdd(&o[3], acc.w * inv);
}

extern "C" void kernel_launch(void* const* d_in, const int* in_sizes, int n_in,
                              void* d_out, int out_size)
{
    const float4* x       = (const float4*)d_in[0];   // [B,T,H] f32
    const int*    lengths = (const int*)d_in[1];      // [B] i32
    const int*    mask    = (const int*)d_in[2];      // [B,T] bool -> i32
    float*        out     = (float*)d_out;            // [B, 2H] f32

    pass1_kernel<<<BB * SS, 128>>>(x, lengths, mask, (float4*)out);
    pass2_kernel<<<BB * COLP * CP, 128>>>(lengths, out);
}